// round 4
// baseline (speedup 1.0000x reference)
#include <cuda_runtime.h>

#define FULL 0xffffffffu
constexpr int NQ  = 8;
constexpr int IND = 512;
constexpr int WPB = 8;           // warps per block
constexpr int TPB = WPB * 32;
constexpr int M4  = 4;           // batch elements per warp pass

__global__ __launch_bounds__(TPB, 2)        // cap regs at 128 -> 2 blocks/SM
void vqc_kernel(const float* __restrict__ h,
                const float* __restrict__ W,
                const float* __restrict__ bpre,
                const float* __restrict__ wts,
                float* __restrict__ out,
                int B)
{
    __shared__ float4 Wsh[NQ * IND / 4];     // 16 KB, W[o][k] as float4
    __shared__ float4 Msh[NQ][2];            // Rz*Ry*Rx per qubit (complex 2x2)
    __shared__ float  Bsh[NQ];

    const int tid  = threadIdx.x;
    const int lane = tid & 31;
    const int wrp  = tid >> 5;

    // Stage W_pre into shared (coalesced)
    #pragma unroll
    for (int k = 0; k < (NQ * IND / 4) / TPB; ++k)
        Wsh[tid + k * TPB] = reinterpret_cast<const float4*>(W)[tid + k * TPB];

    // Batch-independent gate matrices M_w = Rz(g)*Ry(b)*Rx(a), once per block
    if (tid < NQ) {
        Bsh[tid] = bpre[tid];
        float al = 0.5f * wts[tid * 3 + 0];
        float be = 0.5f * wts[tid * 3 + 1];
        float ga = 0.5f * wts[tid * 3 + 2];
        float sa, ca, sb, cb, sg, cg;
        sincosf(al, &sa, &ca);
        sincosf(be, &sb, &cb);
        sincosf(ga, &sg, &cg);
        // Ry*Rx (complex 2x2)
        float r00r =  cb * ca, r00i =  sb * sa;
        float r01r = -sb * ca, r01i = -cb * sa;
        float r10r =  sb * ca, r10i = -cb * sa;
        float r11r =  cb * ca, r11i = -sb * sa;
        // row0 *= e^{-i g/2}, row1 *= e^{+i g/2}
        Msh[tid][0] = make_float4(r00r * cg + r00i * sg,
                                  r00i * cg - r00r * sg,
                                  r01r * cg + r01i * sg,
                                  r01i * cg - r01r * sg);
        Msh[tid][1] = make_float4(r10r * cg - r10i * sg,
                                  r10i * cg + r10r * sg,
                                  r11r * cg - r11i * sg,
                                  r11i * cg + r11r * sg);
    }
    __syncthreads();

    const int w = lane >> 2;     // qubit owned by this lane after reduction
    const int m = lane & 3;      // element-within-pass owned by this lane

    for (int e0 = (blockIdx.x * WPB + wrp) * M4; e0 < B; e0 += gridDim.x * WPB * M4) {
        // ---------- front-load ALL h data for this pass (16 LDG.128, max MLP) ----------
        const float4* hr = reinterpret_cast<const float4*>(h) + (size_t)e0 * (IND / 4);
        float4 hv[M4 * 4];
        #pragma unroll
        for (int mm = 0; mm < M4; ++mm)
            #pragma unroll
            for (int k = 0; k < 4; ++k)
                hv[mm * 4 + k] = hr[mm * (IND / 4) + k * 32 + lane];

        // ---------- GEMM: r[o*4+mm] = <h[e0+mm], W[o]> (partial, this lane's cols) ----
        float r[32];
        #pragma unroll
        for (int i = 0; i < 32; ++i) r[i] = 0.f;

        #pragma unroll
        for (int k = 0; k < 4; ++k) {
            #pragma unroll
            for (int o = 0; o < NQ; ++o) {
                float4 wv = Wsh[o * (IND / 4) + k * 32 + lane];
                #pragma unroll
                for (int mm = 0; mm < M4; ++mm) {
                    float4 hx = hv[mm * 4 + k];
                    r[o * 4 + mm] = fmaf(hx.x, wv.x, fmaf(hx.y, wv.y,
                                    fmaf(hx.z, wv.z, fmaf(hx.w, wv.w, r[o * 4 + mm]))));
                }
            }
        }

        // ---------- exchange-tree reduce: lane L ends with full sum of r[L] ----------
        #pragma unroll
        for (int s = 4; s >= 0; --s) {
            const int d = 1 << s;
            const int half = 1 << s;
            const bool hi = (lane >> s) & 1;
            #pragma unroll
            for (int j = 0; j < half; ++j) {
                float keep = hi ? r[j + half] : r[j];
                float send = hi ? r[j] : r[j + half];
                keep += __shfl_xor_sync(FULL, send, d);
                r[j] = keep;
            }
        }
        float a = r[0];                       // pre-activation for (qubit w, elem m)

        // ---------- single-qubit state & Pauli expectations ----------
        float t = tanhf(a + Bsh[w]) * 1.57079632679489662f;
        t = fminf(fmaxf(t, -3.14159265358979f), 3.14159265358979f);
        float s, c;
        sincosf(0.5f * t, &s, &c);
        float4 m0 = Msh[w][0], m1 = Msh[w][1];
        float v0r = m0.x * c + m0.z * s, v0i = m0.y * c + m0.w * s;
        float v1r = m1.x * c + m1.z * s, v1i = m1.y * c + m1.w * s;
        float x = 2.f * (v0r * v1r + v0i * v1i);
        float y = 2.f * (v0r * v1i - v0i * v1r);
        float z = (v0r * v0r + v0i * v0i) - (v1r * v1r + v1i * v1i);

        // ---------- product scans over the stride-4 lane comb (8 qubits) ----------
        float P = z;                          // inclusive prefix z0..zw
        float G = (w >= 2) ? z : 1.f;         // prefix of z restricted to w>=2
        #pragma unroll
        for (int d = 1; d < 8; d <<= 1) {
            float tp = __shfl_up_sync(FULL, P, 4 * d);
            float tg = __shfl_up_sync(FULL, G, 4 * d);
            if (w >= d) { P *= tp; G *= tg; }
        }
        float Pexc  = __shfl_up_sync(FULL, P, 4);                      // z0..z_{w-1}
        float xnext = __shfl_sync(FULL, x, m + 4 * ((w + 1) & 7));     // x_{w+1 mod 8}
        float x1    = __shfl_sync(FULL, x, m + 4);
        float y0    = __shfl_sync(FULL, y, m);
        float y1    = __shfl_sync(FULL, y, m + 4);
        float z1    = __shfl_sync(FULL, z, m + 4);
        float G6    = __shfl_sync(FULL, G, m + 24);                    // z2..z6
        float G7    = __shfl_sync(FULL, G, m + 28);                    // z2..z7

        // ---------- assemble the 3 observables this lane owns ----------
        float X = (w == 7) ? (x * xnext * x1) : (x * xnext);
        float Y, Z;
        if (w == 0)      { Y = x * y1 * G7;            Z = z1 * G7; }
        else if (w == 7) { Y = -y0 * y1 * G6 * y;      Z = P; }
        else             { Y = Pexc * y * xnext;       Z = P; }

        // ---------- normalize over the 24 outputs of this element ----------
        float ss = X * X + Y * Y + Z * Z;
        ss += __shfl_xor_sync(FULL, ss, 4);
        ss += __shfl_xor_sync(FULL, ss, 8);
        ss += __shfl_xor_sync(FULL, ss, 16);
        float inv = 1.f / fmaxf(sqrtf(ss), 1e-12f);

        int e = e0 + m;
        if (e < B) {
            float* op = out + (size_t)e * 24 + 3 * w;
            op[0] = X * inv;
            op[1] = Y * inv;
            op[2] = Z * inv;
        }
    }
}

extern "C" void kernel_launch(void* const* d_in, const int* in_sizes, int n_in,
                              void* d_out, int out_size)
{
    const float* h    = (const float*)d_in[0];
    const float* W    = (const float*)d_in[1];
    const float* bpre = (const float*)d_in[2];
    const float* wts  = (const float*)d_in[3];
    float* out        = (float*)d_out;

    int B = in_sizes[0] / IND;                      // 16384
    int blocks = (B + WPB * M4 - 1) / (WPB * M4);   // 512 blocks, one pass per warp
    vqc_kernel<<<blocks, TPB>>>(h, W, bpre, wts, out, B);
}

// round 5
// speedup vs baseline: 1.2448x; 1.2448x over previous
#include <cuda_runtime.h>

#define FULL 0xffffffffu
constexpr int NQ  = 8;
constexpr int IND = 512;
constexpr int WPB = 8;           // warps per block (4 teams of 2)
constexpr int TPB = WPB * 32;
constexpr int M4  = 4;           // batch elements per team

__global__ __launch_bounds__(TPB, 2)        // ~85 live regs -> fits 128, 2 blocks/SM
void vqc_kernel(const float* __restrict__ h,
                const float* __restrict__ W,
                const float* __restrict__ bpre,
                const float* __restrict__ wts,
                float* __restrict__ out,
                int B)
{
    __shared__ float4 Wsh[NQ * IND / 4];        // 16 KB
    __shared__ float4 Msh[NQ][2];               // Rz*Ry*Rx per qubit (complex 2x2)
    __shared__ float  Bsh[NQ];
    __shared__ float  tsum[WPB / 2][2][32];     // per-team partial-sum exchange

    const int tid  = threadIdx.x;
    const int lane = tid & 31;
    const int wrp  = tid >> 5;
    const int team = wrp >> 1;
    const int half = wrp & 1;                   // which K-half this warp owns

    // Stage W_pre into shared (coalesced)
    #pragma unroll
    for (int k = 0; k < (NQ * IND / 4) / TPB; ++k)
        Wsh[tid + k * TPB] = reinterpret_cast<const float4*>(W)[tid + k * TPB];

    // Batch-independent gate matrices M_w = Rz(g)*Ry(b)*Rx(a), once per block
    if (tid < NQ) {
        Bsh[tid] = bpre[tid];
        float al = 0.5f * wts[tid * 3 + 0];
        float be = 0.5f * wts[tid * 3 + 1];
        float ga = 0.5f * wts[tid * 3 + 2];
        float sa, ca, sb, cb, sg, cg;
        sincosf(al, &sa, &ca);
        sincosf(be, &sb, &cb);
        sincosf(ga, &sg, &cg);
        float r00r =  cb * ca, r00i =  sb * sa;
        float r01r = -sb * ca, r01i = -cb * sa;
        float r10r =  sb * ca, r10i = -cb * sa;
        float r11r =  cb * ca, r11i = -sb * sa;
        Msh[tid][0] = make_float4(r00r * cg + r00i * sg,
                                  r00i * cg - r00r * sg,
                                  r01r * cg + r01i * sg,
                                  r01i * cg - r01r * sg);
        Msh[tid][1] = make_float4(r10r * cg - r10i * sg,
                                  r10i * cg + r10r * sg,
                                  r11r * cg - r11i * sg,
                                  r11i * cg + r11r * sg);
    }
    __syncthreads();

    const int w = lane >> 2;     // qubit owned by this lane after reduction
    const int m = lane & 3;      // element-within-team owned by this lane

    const int e0 = (blockIdx.x * (WPB / 2) + team) * M4;
    if (e0 < B) {
        // ---------- front-load this warp's K-half of h (8 LDG.128) ----------
        const float4* hr = reinterpret_cast<const float4*>(h) + (size_t)e0 * (IND / 4);
        const int kbase = half * 2;             // this warp covers k = kbase, kbase+1
        float4 hv[M4 * 2];
        #pragma unroll
        for (int mm = 0; mm < M4; ++mm)
            #pragma unroll
            for (int kk = 0; kk < 2; ++kk)
                hv[mm * 2 + kk] = hr[mm * (IND / 4) + (kbase + kk) * 32 + lane];

        // ---------- partial GEMM over this K-half ----------
        float r[32];
        #pragma unroll
        for (int i = 0; i < 32; ++i) r[i] = 0.f;

        #pragma unroll
        for (int kk = 0; kk < 2; ++kk) {
            #pragma unroll
            for (int o = 0; o < NQ; ++o) {
                float4 wv = Wsh[o * (IND / 4) + (kbase + kk) * 32 + lane];
                #pragma unroll
                for (int mm = 0; mm < M4; ++mm) {
                    float4 hx = hv[mm * 2 + kk];
                    r[o * 4 + mm] = fmaf(hx.x, wv.x, fmaf(hx.y, wv.y,
                                    fmaf(hx.z, wv.z, fmaf(hx.w, wv.w, r[o * 4 + mm]))));
                }
            }
        }

        // ---------- exchange-tree reduce: lane L ends with half-sum of r[L] ----------
        #pragma unroll
        for (int s = 4; s >= 0; --s) {
            const int d = 1 << s;
            const int hsz = 1 << s;
            const bool hi = (lane >> s) & 1;
            #pragma unroll
            for (int j = 0; j < hsz; ++j) {
                float keep = hi ? r[j + hsz] : r[j];
                float send = hi ? r[j] : r[j + hsz];
                keep += __shfl_xor_sync(FULL, send, d);
                r[j] = keep;
            }
        }

        // ---------- cross-warp combine (32 floats via smem + named barrier) ----------
        tsum[team][half][lane] = r[0];
        asm volatile("bar.sync %0, 64;" :: "r"(team + 1) : "memory");
        float a = r[0] + tsum[team][half ^ 1][lane];

        // ---------- single-qubit state & Pauli expectations ----------
        float t = tanhf(a + Bsh[w]) * 1.57079632679489662f;
        t = fminf(fmaxf(t, -3.14159265358979f), 3.14159265358979f);
        float s, c;
        sincosf(0.5f * t, &s, &c);
        float4 m0 = Msh[w][0], m1 = Msh[w][1];
        float v0r = m0.x * c + m0.z * s, v0i = m0.y * c + m0.w * s;
        float v1r = m1.x * c + m1.z * s, v1i = m1.y * c + m1.w * s;
        float x = 2.f * (v0r * v1r + v0i * v1i);
        float y = 2.f * (v0r * v1i - v0i * v1r);
        float z = (v0r * v0r + v0i * v0i) - (v1r * v1r + v1i * v1i);

        // ---------- product scans over the stride-4 lane comb (8 qubits) ----------
        float P = z;                          // inclusive prefix z0..zw
        float G = (w >= 2) ? z : 1.f;         // prefix of z restricted to w>=2
        #pragma unroll
        for (int d = 1; d < 8; d <<= 1) {
            float tp = __shfl_up_sync(FULL, P, 4 * d);
            float tg = __shfl_up_sync(FULL, G, 4 * d);
            if (w >= d) { P *= tp; G *= tg; }
        }
        float Pexc  = __shfl_up_sync(FULL, P, 4);                      // z0..z_{w-1}
        float xnext = __shfl_sync(FULL, x, m + 4 * ((w + 1) & 7));     // x_{w+1 mod 8}
        float x1    = __shfl_sync(FULL, x, m + 4);
        float y0    = __shfl_sync(FULL, y, m);
        float y1    = __shfl_sync(FULL, y, m + 4);
        float z1    = __shfl_sync(FULL, z, m + 4);
        float G6    = __shfl_sync(FULL, G, m + 24);                    // z2..z6
        float G7    = __shfl_sync(FULL, G, m + 28);                    // z2..z7

        // ---------- assemble the 3 observables this lane owns ----------
        float X = (w == 7) ? (x * xnext * x1) : (x * xnext);
        float Y, Z;
        if (w == 0)      { Y = x * y1 * G7;            Z = z1 * G7; }
        else if (w == 7) { Y = -y0 * y1 * G6 * y;      Z = P; }
        else             { Y = Pexc * y * xnext;       Z = P; }

        // ---------- normalize over the 24 outputs of this element ----------
        float ss = X * X + Y * Y + Z * Z;
        ss += __shfl_xor_sync(FULL, ss, 4);
        ss += __shfl_xor_sync(FULL, ss, 8);
        ss += __shfl_xor_sync(FULL, ss, 16);
        float inv = 1.f / fmaxf(sqrtf(ss), 1e-12f);

        int e = e0 + m;
        if (half == 1 && e < B) {            // one warp of the pair stores
            float* op = out + (size_t)e * 24 + 3 * w;
            op[0] = X * inv;
            op[1] = Y * inv;
            op[2] = Z * inv;
        }
    }
}

extern "C" void kernel_launch(void* const* d_in, const int* in_sizes, int n_in,
                              void* d_out, int out_size)
{
    const float* h    = (const float*)d_in[0];
    const float* W    = (const float*)d_in[1];
    const float* bpre = (const float*)d_in[2];
    const float* wts  = (const float*)d_in[3];
    float* out        = (float*)d_out;

    int B = in_sizes[0] / IND;                              // 16384
    int teams_per_blk = WPB / 2;                            // 4
    int blocks = (B + teams_per_blk * M4 - 1) / (teams_per_blk * M4);   // 1024
    vqc_kernel<<<blocks, TPB>>>(h, W, bpre, wts, out, B);
}

// round 7
// speedup vs baseline: 1.7173x; 1.3795x over previous
#include <cuda_runtime.h>
#include <cstdint>

#define FULL 0xffffffffu
constexpr int NQ  = 8;
constexpr int IND = 512;
constexpr int WPB = 4;            // warps per block
constexpr int TPB = WPB * 32;
constexpr int M4  = 4;            // batch elements per warp pass
constexpr int GRID = 296;         // 2 blocks/SM on 148 SMs
// dynamic smem: h double-buffer, WPB * 2 stages * (M4*128) float4 = 64 KB
constexpr int STAGE_F4 = M4 * 128;                  // 512 float4 per stage
constexpr size_t DYN_SMEM = (size_t)WPB * 2 * STAGE_F4 * sizeof(float4);

__device__ __forceinline__ void cp_async16(void* smem_dst, const void* gmem_src) {
    unsigned int s = (unsigned int)__cvta_generic_to_shared(smem_dst);
    asm volatile("cp.async.cg.shared.global [%0], [%1], 16;" :: "r"(s), "l"(gmem_src));
}
__device__ __forceinline__ void cp_commit() {
    asm volatile("cp.async.commit_group;");
}
__device__ __forceinline__ void cp_wait1() {
    asm volatile("cp.async.wait_group 1;");
}

__global__ __launch_bounds__(TPB, 2)
void vqc_kernel(const float* __restrict__ h,
                const float* __restrict__ W,
                const float* __restrict__ bpre,
                const float* __restrict__ wts,
                float* __restrict__ out,
                int B)
{
    extern __shared__ float4 Hbuf[];            // [WPB][2][STAGE_F4]
    __shared__ float4 Wsh[NQ * IND / 4];        // 16 KB
    __shared__ float4 Msh[NQ][2];
    __shared__ float  Bsh[NQ];

    const int tid  = threadIdx.x;
    const int lane = tid & 31;
    const int wrp  = tid >> 5;

    // Stage W_pre into shared (coalesced)
    #pragma unroll
    for (int k = 0; k < (NQ * IND / 4) / TPB; ++k)
        Wsh[tid + k * TPB] = reinterpret_cast<const float4*>(W)[tid + k * TPB];

    // Batch-independent gate matrices M_w = Rz(g)*Ry(b)*Rx(a)
    if (tid < NQ) {
        Bsh[tid] = bpre[tid];
        float al = 0.5f * wts[tid * 3 + 0];
        float be = 0.5f * wts[tid * 3 + 1];
        float ga = 0.5f * wts[tid * 3 + 2];
        float sa, ca, sb, cb, sg, cg;
        sincosf(al, &sa, &ca);
        sincosf(be, &sb, &cb);
        sincosf(ga, &sg, &cg);
        float r00r =  cb * ca, r00i =  sb * sa;
        float r01r = -sb * ca, r01i = -cb * sa;
        float r10r =  sb * ca, r10i = -cb * sa;
        float r11r =  cb * ca, r11i = -sb * sa;
        Msh[tid][0] = make_float4(r00r * cg + r00i * sg,
                                  r00i * cg - r00r * sg,
                                  r01r * cg + r01i * sg,
                                  r01i * cg - r01r * sg);
        Msh[tid][1] = make_float4(r10r * cg - r10i * sg,
                                  r10i * cg + r10r * sg,
                                  r11r * cg - r11i * sg,
                                  r11i * cg + r11r * sg);
    }
    __syncthreads();

    const int w = lane >> 2;      // qubit owned by this lane after reduction
    const int m = lane & 3;       // element-within-pass owned by this lane

    float4* const myH = Hbuf + wrp * 2 * STAGE_F4;
    const int STEP = GRID * WPB * M4;                 // elements per sweep

    // ---- prefetch first stage ----
    int e0 = (blockIdx.x * WPB + wrp) * M4;
    if (e0 < B) {
        const float4* hr = reinterpret_cast<const float4*>(h) + (size_t)e0 * (IND / 4);
        #pragma unroll
        for (int i = 0; i < M4 * 4; ++i)
            cp_async16(&myH[i * 32 + lane], &hr[i * 32 + lane]);
    }
    cp_commit();

    int buf = 0;
    for (; e0 < B; e0 += STEP, buf ^= 1) {
        // ---- prefetch next stage while computing this one ----
        int en = e0 + STEP;
        if (en < B) {
            const float4* hr = reinterpret_cast<const float4*>(h) + (size_t)en * (IND / 4);
            float4* dst = myH + (buf ^ 1) * STAGE_F4;
            #pragma unroll
            for (int i = 0; i < M4 * 4; ++i)
                cp_async16(&dst[i * 32 + lane], &hr[i * 32 + lane]);
        }
        cp_commit();
        cp_wait1();                    // current stage (all but newest group) is ready

        const float4* hs = myH + buf * STAGE_F4;

        // ---------- GEMM: r[o*4+mm] = <h[e0+mm], W[o]> (lane's K-slice) ----------
        float r[32];
        #pragma unroll
        for (int i = 0; i < 32; ++i) r[i] = 0.f;

        #pragma unroll
        for (int k = 0; k < 4; ++k) {
            float4 hv[M4];
            #pragma unroll
            for (int mm = 0; mm < M4; ++mm)
                hv[mm] = hs[mm * 128 + k * 32 + lane];
            #pragma unroll
            for (int o = 0; o < NQ; ++o) {
                float4 wv = Wsh[o * (IND / 4) + k * 32 + lane];
                #pragma unroll
                for (int mm = 0; mm < M4; ++mm) {
                    r[o * 4 + mm] = fmaf(hv[mm].x, wv.x, fmaf(hv[mm].y, wv.y,
                                    fmaf(hv[mm].z, wv.z, fmaf(hv[mm].w, wv.w, r[o * 4 + mm]))));
                }
            }
        }

        // ---------- exchange-tree reduce: lane L ends with full sum of r[L] ----------
        #pragma unroll
        for (int s = 4; s >= 0; --s) {
            const int d = 1 << s;
            const int hsz = 1 << s;
            const bool hi = (lane >> s) & 1;
            #pragma unroll
            for (int j = 0; j < hsz; ++j) {
                float keep = hi ? r[j + hsz] : r[j];
                float send = hi ? r[j] : r[j + hsz];
                keep += __shfl_xor_sync(FULL, send, d);
                r[j] = keep;
            }
        }
        float a = r[0];                // pre-activation for (qubit w, elem m)

        // ---------- single-qubit state & Pauli expectations ----------
        float t = tanhf(a + Bsh[w]) * 1.57079632679489662f;
        t = fminf(fmaxf(t, -3.14159265358979f), 3.14159265358979f);
        float s, c;
        sincosf(0.5f * t, &s, &c);
        float4 m0 = Msh[w][0], m1 = Msh[w][1];
        float v0r = m0.x * c + m0.z * s, v0i = m0.y * c + m0.w * s;
        float v1r = m1.x * c + m1.z * s, v1i = m1.y * c + m1.w * s;
        float x = 2.f * (v0r * v1r + v0i * v1i);
        float y = 2.f * (v0r * v1i - v0i * v1r);
        float z = (v0r * v0r + v0i * v0i) - (v1r * v1r + v1i * v1i);

        // ---------- product scans over the stride-4 lane comb (8 qubits) ----------
        float P = z;                   // inclusive prefix z0..zw
        float G = (w >= 2) ? z : 1.f;  // prefix of z restricted to w>=2
        #pragma unroll
        for (int d = 1; d < 8; d <<= 1) {
            float tp = __shfl_up_sync(FULL, P, 4 * d);
            float tg = __shfl_up_sync(FULL, G, 4 * d);
            if (w >= d) { P *= tp; G *= tg; }
        }
        float Pexc  = __shfl_up_sync(FULL, P, 4);                   // z0..z_{w-1}
        float xnext = __shfl_sync(FULL, x, m + 4 * ((w + 1) & 7));  // x_{w+1 mod 8}
        float x1    = __shfl_sync(FULL, x, m + 4);
        float y0    = __shfl_sync(FULL, y, m);
        float y1    = __shfl_sync(FULL, y, m + 4);
        float z1    = __shfl_sync(FULL, z, m + 4);
        float G6    = __shfl_sync(FULL, G, m + 24);                 // z2..z6
        float G7    = __shfl_sync(FULL, G, m + 28);                 // z2..z7

        // ---------- assemble the 3 observables this lane owns ----------
        float X = (w == 7) ? (x * xnext * x1) : (x * xnext);
        float Y, Z;
        if (w == 0)      { Y = x * y1 * G7;            Z = z1 * G7; }
        else if (w == 7) { Y = -y0 * y1 * G6 * y;      Z = P; }
        else             { Y = Pexc * y * xnext;       Z = P; }

        // ---------- normalize over the 24 outputs of this element ----------
        float ss = X * X + Y * Y + Z * Z;
        ss += __shfl_xor_sync(FULL, ss, 4);
        ss += __shfl_xor_sync(FULL, ss, 8);
        ss += __shfl_xor_sync(FULL, ss, 16);
        float inv = 1.f / fmaxf(sqrtf(ss), 1e-12f);

        int e = e0 + m;
        if (e < B) {
            float* op = out + (size_t)e * 24 + 3 * w;
            op[0] = X * inv;
            op[1] = Y * inv;
            op[2] = Z * inv;
        }
    }
}

extern "C" void kernel_launch(void* const* d_in, const int* in_sizes, int n_in,
                              void* d_out, int out_size)
{
    const float* h    = (const float*)d_in[0];
    const float* W    = (const float*)d_in[1];
    const float* bpre = (const float*)d_in[2];
    const float* wts  = (const float*)d_in[3];
    float* out        = (float*)d_out;

    int B = in_sizes[0] / IND;                      // 16384

    static bool attr_done = false;                  // idempotent attribute raise
    if (!attr_done) {
        cudaFuncSetAttribute(vqc_kernel,
                             cudaFuncAttributeMaxDynamicSharedMemorySize,
                             (int)DYN_SMEM);
        attr_done = true;
    }
    vqc_kernel<<<GRID, TPB, DYN_SMEM>>>(h, W, bpre, wts, out, B);
}